// round 8
// baseline (speedup 1.0000x reference)
#include <cuda_runtime.h>
#include <cstddef>

// ---------------- scratch (no allocations allowed) ----------------
__device__ float g_Wf[3 * 256 * 256];   // folded QKV weights
__device__ float g_bf[768];             // folded QKV biases
__device__ float g_q[4096 * 256];
__device__ float g_k[768 * 256];
__device__ float g_v[768 * 256];
__device__ float g_ctx[4096 * 256];
__device__ float g_att[4096 * 256];
__device__ float g_fused[4096 * 256];
__device__ float g_h2[4096 * 128];

// ---------------- generic tiled SGEMM: C = A @ op(W) + bias ----------------
// A: [M,K] row-major. WT=true: W is [N,K] (use W^T). WT=false: W is [K,N].
// Tiles 64x64x16, 256 threads, 4x4 per-thread microtile, float4 everywhere.
// Requires M%64==0, N%64==0, K%16==0 (all shapes here satisfy this).
template <bool RELU, bool WT>
__global__ __launch_bounds__(256) void gemm_kernel(
    const float* __restrict__ A, const float* __restrict__ W,
    const float* __restrict__ bias, float* __restrict__ C,
    int M, int N, int K)
{
    __shared__ float As[16][64];  // As[k][m]
    __shared__ float Bs[16][64];  // Bs[k][n]
    const int bm = blockIdx.y * 64;
    const int bn = blockIdx.x * 64;
    const int tid = threadIdx.x;
    const int tm = (tid >> 4) << 2;   // 0..60
    const int tn = (tid & 15) << 2;   // 0..60

    float acc[4][4] = {};

    for (int k0 = 0; k0 < K; k0 += 16) {
        {   // load A tile (64x16) as 256 float4
            int m = tid >> 2, k4 = (tid & 3) << 2;
            float4 a4 = *(const float4*)(A + (size_t)(bm + m) * K + k0 + k4);
            As[k4 + 0][m] = a4.x; As[k4 + 1][m] = a4.y;
            As[k4 + 2][m] = a4.z; As[k4 + 3][m] = a4.w;
        }
        if (WT) {   // W[N,K]
            int n = tid >> 2, k4 = (tid & 3) << 2;
            float4 w4 = *(const float4*)(W + (size_t)(bn + n) * K + k0 + k4);
            Bs[k4 + 0][n] = w4.x; Bs[k4 + 1][n] = w4.y;
            Bs[k4 + 2][n] = w4.z; Bs[k4 + 3][n] = w4.w;
        } else {    // W[K,N]
            int kk = tid >> 4, n4 = (tid & 15) << 2;
            float4 w4 = *(const float4*)(W + (size_t)(k0 + kk) * N + bn + n4);
            Bs[kk][n4 + 0] = w4.x; Bs[kk][n4 + 1] = w4.y;
            Bs[kk][n4 + 2] = w4.z; Bs[kk][n4 + 3] = w4.w;
        }
        __syncthreads();

        #pragma unroll
        for (int kk = 0; kk < 16; kk++) {
            float4 a4 = *(const float4*)(&As[kk][tm]);
            float4 w4 = *(const float4*)(&Bs[kk][tn]);
            float a[4] = {a4.x, a4.y, a4.z, a4.w};
            float w[4] = {w4.x, w4.y, w4.z, w4.w};
            #pragma unroll
            for (int i = 0; i < 4; i++)
                #pragma unroll
                for (int j = 0; j < 4; j++)
                    acc[i][j] += a[i] * w[j];
        }
        __syncthreads();
    }

    #pragma unroll
    for (int i = 0; i < 4; i++) {
        float4 r;
        float* pr = &r.x;
        #pragma unroll
        for (int j = 0; j < 4; j++) {
            float bv = bias ? bias[bn + tn + j] : 0.0f;
            float val = acc[i][j] + bv;
            if (RELU) val = fmaxf(val, 0.0f);
            pr[j] = val;
        }
        *(float4*)(C + (size_t)(bm + tm + i) * N + bn + tn) = r;
    }
}

// ---------------- folded QKV bias: bf[i] = bin[i] + Win[i,:] . (bs|bt) ----
__global__ void fold_bias_kernel(const float* __restrict__ Win,
                                 const float* __restrict__ bin,
                                 const float* __restrict__ bs,
                                 const float* __restrict__ bt,
                                 float* __restrict__ bf)
{
    int i = blockIdx.x * 256 + threadIdx.x;   // 0..767
    if (i >= 768) return;
    const float* src = (i < 256) ? bs : bt;
    float acc = bin[i];
    const float* wr = Win + (size_t)i * 256;
    #pragma unroll 4
    for (int kk = 0; kk < 256; kk++) acc += wr[kk] * src[kk];
    bf[i] = acc;
}

// ---------------- attention: one (b,h) pair per 2 blocks; 1 q-row/thread ----
// logits[b,h,n,s] = scale * q[b,n,h,:].k[b,s,h,:]; softmax over s;
// ctx[b,n,h,:] = attn . v  -> stored as [4096,256] with col h*32+d
__global__ __launch_bounds__(256) void attn_kernel(
    const float* __restrict__ q, const float* __restrict__ k,
    const float* __restrict__ v, float* __restrict__ ctx)
{
    __shared__ float ks[96][32];
    __shared__ float vsm[96][32];
    const int b = blockIdx.z, h = blockIdx.y;
    const int n = blockIdx.x * 256 + threadIdx.x;

    for (int i = threadIdx.x; i < 96 * 32; i += 256) {
        int s = i >> 5, d = i & 31;
        size_t src = (size_t)(b * 96 + s) * 256 + h * 32 + d;
        ks[s][d]  = k[src];
        vsm[s][d] = v[src];
    }
    __syncthreads();

    const float scale = 0.17677669529663687f;   // 1/sqrt(32)
    float qv[32];
    const float* qrow = q + (size_t)(b * 512 + n) * 256 + h * 32;
    #pragma unroll
    for (int d = 0; d < 32; d++) qv[d] = qrow[d] * scale;

    float lg[96];
    float mx = -1e30f;
    #pragma unroll 2
    for (int s = 0; s < 96; s++) {
        float a = 0.0f;
        #pragma unroll
        for (int d = 0; d < 32; d++) a += qv[d] * ks[s][d];
        lg[s] = a;
        mx = fmaxf(mx, a);
    }

    float acc[32];
    #pragma unroll
    for (int d = 0; d < 32; d++) acc[d] = 0.0f;
    float sum = 0.0f;
    #pragma unroll 2
    for (int s = 0; s < 96; s++) {
        float e = __expf(lg[s] - mx);     // exactly one exp per logit
        sum += e;
        #pragma unroll
        for (int d = 0; d < 32; d++) acc[d] += e * vsm[s][d];
    }
    float inv = 1.0f / sum;

    float* crow = ctx + (size_t)(b * 512 + n) * 256 + h * 32;
    #pragma unroll
    for (int d = 0; d < 32; d++) crow[d] = acc[d] * inv;
}

// ---------------- final: y = h2 @ Wo2^T + bo2, broadcast over S ----------
// thread g -> (row = g>>2, o = g&3); warp writes are 128B-contiguous per s.
__global__ __launch_bounds__(256) void final_kernel(
    const float* __restrict__ h2, const float* __restrict__ Wo2,
    const float* __restrict__ bo2, float* __restrict__ out)
{
    int g = blockIdx.x * 256 + threadIdx.x;   // 0..16383
    int o = g & 3;
    int row = g >> 2;        // 0..4095
    int b = row >> 9;
    int n = row & 511;

    float acc = bo2[o];
    const float* hr = h2 + (size_t)row * 128;
    const float* wr = Wo2 + (size_t)o * 128;
    #pragma unroll 8
    for (int kk = 0; kk < 128; kk++) acc += hr[kk] * wr[kk];

    // out[b][s][n][o], s stride = 512*4 = 2048 floats
    float* base = out + (size_t)b * (96 * 512 * 4) + (size_t)n * 4 + o;
    #pragma unroll 4
    for (int s = 0; s < 96; s++) base[(size_t)s * 2048] = acc;
}

// ---------------- launch ----------------
extern "C" void kernel_launch(void* const* d_in, const int* in_sizes, int n_in,
                              void* d_out, int out_size)
{
    const float* spatial  = (const float*)d_in[0];   // [8,512,256]
    const float* temporal = (const float*)d_in[1];   // [8,96,256]
    const float* Ws_  = (const float*)d_in[2];       // [256,256]
    const float* bs_  = (const float*)d_in[3];
    const float* Wt_  = (const float*)d_in[4];
    const float* bt_  = (const float*)d_in[5];
    const float* Win  = (const float*)d_in[6];       // [768,256]
    const float* bin_ = (const float*)d_in[7];       // [768]
    const float* Wao  = (const float*)d_in[8];       // [256,256]
    const float* bao  = (const float*)d_in[9];
    const float* W1   = (const float*)d_in[10];      // [256,256]
    const float* b1   = (const float*)d_in[11];
    const float* Wo1  = (const float*)d_in[12];      // [128,256]
    const float* bo1  = (const float*)d_in[13];
    const float* Wo2  = (const float*)d_in[14];      // [4,128]
    const float* bo2  = (const float*)d_in[15];
    float* out = (float*)d_out;

    float *pWf, *pbf, *pq, *pk, *pv, *pctx, *patt, *pfused, *ph2;
    cudaGetSymbolAddress((void**)&pWf,    g_Wf);
    cudaGetSymbolAddress((void**)&pbf,    g_bf);
    cudaGetSymbolAddress((void**)&pq,     g_q);
    cudaGetSymbolAddress((void**)&pk,     g_k);
    cudaGetSymbolAddress((void**)&pv,     g_v);
    cudaGetSymbolAddress((void**)&pctx,   g_ctx);
    cudaGetSymbolAddress((void**)&patt,   g_att);
    cudaGetSymbolAddress((void**)&pfused, g_fused);
    cudaGetSymbolAddress((void**)&ph2,    g_h2);

    const dim3 blk(256);

    // Fold Wq'=Wq@Ws, Wk'=Wk@Wt, Wv'=Wv@Wt  (A[256,256] @ W[K=256,N=256])
    gemm_kernel<false, false><<<dim3(4, 4), blk>>>(Win,           Ws_, nullptr, pWf,           256, 256, 256);
    gemm_kernel<false, false><<<dim3(4, 4), blk>>>(Win + 65536,   Wt_, nullptr, pWf + 65536,   256, 256, 256);
    gemm_kernel<false, false><<<dim3(4, 4), blk>>>(Win + 131072,  Wt_, nullptr, pWf + 131072,  256, 256, 256);
    fold_bias_kernel<<<3, 256>>>(Win, bin_, bs_, bt_, pbf);

    // q = spatial @ Wq'^T + bq'   [4096,256]
    gemm_kernel<false, true><<<dim3(4, 64), blk>>>(spatial,  pWf,          pbf,       pq, 4096, 256, 256);
    // k,v = temporal @ {Wk',Wv'}^T + b  [768,256]
    gemm_kernel<false, true><<<dim3(4, 12), blk>>>(temporal, pWf + 65536,  pbf + 256, pk,  768, 256, 256);
    gemm_kernel<false, true><<<dim3(4, 12), blk>>>(temporal, pWf + 131072, pbf + 512, pv,  768, 256, 256);

    // attention -> ctx [4096,256]
    attn_kernel<<<dim3(2, 8, 8), blk>>>(pq, pk, pv, pctx);

    // attended = ctx @ Wao^T + bao
    gemm_kernel<false, true><<<dim3(4, 64), blk>>>(pctx,   Wao, bao, patt,   4096, 256, 256);
    // fused = relu(attended @ W1^T + b1)
    gemm_kernel<true,  true><<<dim3(4, 64), blk>>>(patt,   W1,  b1,  pfused, 4096, 256, 256);
    // h2 = relu(fused @ Wo1^T + bo1)   [4096,128]
    gemm_kernel<true,  true><<<dim3(2, 64), blk>>>(pfused, Wo1, bo1, ph2,    4096, 128, 256);

    // y = h2 @ Wo2^T + bo2, broadcast to [8,96,512,4]
    final_kernel<<<64, 256>>>(ph2, Wo2, bo2, out);
}

// round 9
// speedup vs baseline: 1.6472x; 1.6472x over previous
#include <cuda_runtime.h>
#include <cstddef>

// ---------------- scratch (no allocations allowed) ----------------
__device__ float g_Wf[3 * 256 * 256];   // folded QKV weights
__device__ float g_bf[768];             // folded QKV biases
__device__ float g_q[4096 * 256];
__device__ float g_k[768 * 256];
__device__ float g_v[768 * 256];
__device__ float g_ctx[4096 * 256];
__device__ float g_att[4096 * 256];
__device__ float g_fused[4096 * 256];
__device__ float g_h2[4096 * 128];

// ---------------- shared tile GEMM body (64x64x16, prefetch-pipelined) ----
// Computes C[bm:bm+64, bn:bn+64] = A[bm:,:K] @ op(W) (+bias)(+relu)
// WT=true: W is [N,K] (uses W^T). WT=false: W is [K,N].
template <bool WT>
__device__ __forceinline__ void gemm_tile(
    const float* __restrict__ A, const float* __restrict__ W,
    const float* __restrict__ bias, float* __restrict__ C,
    int K, int N, int bm, int bn, bool relu)
{
    __shared__ float As[16][64];  // As[k][m]
    __shared__ float Bs[16][64];  // Bs[k][n]
    const int tid = threadIdx.x;
    const int tm = (tid >> 4) << 2;   // 0..60
    const int tn = (tid & 15) << 2;   // 0..60

    // loader mapping
    const int am = tid >> 2, ak = (tid & 3) << 2;      // A: (row am, k ak..ak+3)
    const int wn = tid >> 2, wk = (tid & 3) << 2;      // WT: (row bn+wn, k wk..)
    const int wkk = tid >> 4, wn4 = (tid & 15) << 2;   // !WT: (k wkk, col bn+wn4)

    // prefetch tile 0
    float4 a_pref = *(const float4*)(A + (size_t)(bm + am) * K + ak);
    float4 w_pref;
    if (WT) w_pref = *(const float4*)(W + (size_t)(bn + wn) * K + wk);
    else    w_pref = *(const float4*)(W + (size_t)wkk * N + bn + wn4);

    float acc[4][4] = {};

    for (int k0 = 0; k0 < K; k0 += 16) {
        __syncthreads();   // previous tile fully consumed
        As[ak + 0][am] = a_pref.x; As[ak + 1][am] = a_pref.y;
        As[ak + 2][am] = a_pref.z; As[ak + 3][am] = a_pref.w;
        if (WT) {
            Bs[wk + 0][wn] = w_pref.x; Bs[wk + 1][wn] = w_pref.y;
            Bs[wk + 2][wn] = w_pref.z; Bs[wk + 3][wn] = w_pref.w;
        } else {
            Bs[wkk][wn4 + 0] = w_pref.x; Bs[wkk][wn4 + 1] = w_pref.y;
            Bs[wkk][wn4 + 2] = w_pref.z; Bs[wkk][wn4 + 3] = w_pref.w;
        }
        __syncthreads();

        // prefetch next tile while computing this one
        if (k0 + 16 < K) {
            a_pref = *(const float4*)(A + (size_t)(bm + am) * K + k0 + 16 + ak);
            if (WT) w_pref = *(const float4*)(W + (size_t)(bn + wn) * K + k0 + 16 + wk);
            else    w_pref = *(const float4*)(W + (size_t)(k0 + 16 + wkk) * N + bn + wn4);
        }

        #pragma unroll
        for (int kk = 0; kk < 16; kk++) {
            float4 a4 = *(const float4*)(&As[kk][tm]);
            float4 w4 = *(const float4*)(&Bs[kk][tn]);
            float a[4] = {a4.x, a4.y, a4.z, a4.w};
            float w[4] = {w4.x, w4.y, w4.z, w4.w};
            #pragma unroll
            for (int i = 0; i < 4; i++)
                #pragma unroll
                for (int j = 0; j < 4; j++)
                    acc[i][j] += a[i] * w[j];
        }
    }

    #pragma unroll
    for (int i = 0; i < 4; i++) {
        float4 r;
        float* pr = &r.x;
        #pragma unroll
        for (int j = 0; j < 4; j++) {
            float bv = bias ? bias[bn + tn + j] : 0.0f;
            float val = acc[i][j] + bv;
            if (relu) val = fmaxf(val, 0.0f);
            pr[j] = val;
        }
        *(float4*)(C + (size_t)(bm + tm + i) * N + bn + tn) = r;
    }
}

// ---------------- generic big GEMM (WT=true path) --------------------------
__global__ __launch_bounds__(256) void gemm_wt_kernel(
    const float* __restrict__ A, const float* __restrict__ W,
    const float* __restrict__ bias, float* __restrict__ C,
    int N, int K, int relu)
{
    gemm_tile<true>(A, W, bias, C, K, N, blockIdx.y * 64, blockIdx.x * 64,
                    relu != 0);
}

// ---------------- single-launch weight fold: Wf = Win @ (Ws|Wt) ------------
// grid (4, 12): by<4 -> rows 0..255 use Ws; by>=4 -> Wt. C[i,j]=sum Win[i,k]*W[k,j]
__global__ __launch_bounds__(256) void fold_gemm_kernel(
    const float* __restrict__ Win, const float* __restrict__ Ws,
    const float* __restrict__ Wt, float* __restrict__ Wf)
{
    const float* W = (blockIdx.y < 4) ? Ws : Wt;
    gemm_tile<false>(Win, W, nullptr, Wf, 256, 256,
                     blockIdx.y * 64, blockIdx.x * 64, false);
}

// ---------------- fast folded bias: warp per output -----------------------
__global__ __launch_bounds__(256) void fold_bias_kernel(
    const float* __restrict__ Win, const float* __restrict__ bin,
    const float* __restrict__ bs, const float* __restrict__ bt,
    float* __restrict__ bf)
{
    int w = (blockIdx.x * 256 + threadIdx.x) >> 5;   // warp id = output 0..767
    int lane = threadIdx.x & 31;
    if (w >= 768) return;
    const float* src = (w < 256) ? bs : bt;
    const float* wr = Win + (size_t)w * 256;
    float acc = 0.0f;
    #pragma unroll
    for (int k = 0; k < 256; k += 32) acc += wr[k + lane] * src[k + lane];
    #pragma unroll
    for (int o = 16; o; o >>= 1) acc += __shfl_xor_sync(0xffffffffu, acc, o);
    if (lane == 0) bf[w] = bin[w] + acc;
}

// ---------------- merged QKV projection (one launch, 352 blocks) ----------
// blocks [0,256): q = spatial@Wq'^T  (4x64 tile grid over 4096x256)
// blocks [256,304): k = temporal@Wk'^T  (4x12)
// blocks [304,352): v = temporal@Wv'^T  (4x12)
__global__ __launch_bounds__(256) void qkv_kernel(
    const float* __restrict__ spatial, const float* __restrict__ temporal,
    const float* __restrict__ Wf, const float* __restrict__ bf,
    float* __restrict__ q, float* __restrict__ k, float* __restrict__ v)
{
    int bid = blockIdx.x;
    const float* A; const float* W; const float* bias; float* C;
    int bx, by;
    if (bid < 256) {
        A = spatial;  W = Wf;           bias = bf;       C = q;
        bx = bid & 3; by = bid >> 2;
    } else if (bid < 304) {
        int t = bid - 256;
        A = temporal; W = Wf + 65536;   bias = bf + 256; C = k;
        bx = t & 3;   by = t >> 2;
    } else {
        int t = bid - 304;
        A = temporal; W = Wf + 131072;  bias = bf + 512; C = v;
        bx = t & 3;   by = t >> 2;
    }
    gemm_tile<true>(A, W, bias, C, 256, 256, by * 64, bx * 64, false);
}

// ---------------- attention: one (b,h) per 2 blocks; 1 q-row/thread -------
__global__ __launch_bounds__(256) void attn_kernel(
    const float* __restrict__ q, const float* __restrict__ k,
    const float* __restrict__ v, float* __restrict__ ctx)
{
    __shared__ float ks[96][32];
    __shared__ float vsm[96][32];
    const int b = blockIdx.z, h = blockIdx.y;
    const int n = blockIdx.x * 256 + threadIdx.x;

    for (int i = threadIdx.x; i < 96 * 32; i += 256) {
        int s = i >> 5, d = i & 31;
        size_t src = (size_t)(b * 96 + s) * 256 + h * 32 + d;
        ks[s][d]  = k[src];
        vsm[s][d] = v[src];
    }
    __syncthreads();

    const float scale = 0.17677669529663687f;   // 1/sqrt(32)
    float qv[32];
    const float* qrow = q + (size_t)(b * 512 + n) * 256 + h * 32;
    #pragma unroll
    for (int d = 0; d < 32; d++) qv[d] = qrow[d] * scale;

    float lg[96];
    float mx = -1e30f;
    #pragma unroll 2
    for (int s = 0; s < 96; s++) {
        float a = 0.0f;
        #pragma unroll
        for (int d = 0; d < 32; d++) a += qv[d] * ks[s][d];
        lg[s] = a;
        mx = fmaxf(mx, a);
    }

    float acc[32];
    #pragma unroll
    for (int d = 0; d < 32; d++) acc[d] = 0.0f;
    float sum = 0.0f;
    #pragma unroll 2
    for (int s = 0; s < 96; s++) {
        float e = __expf(lg[s] - mx);
        sum += e;
        #pragma unroll
        for (int d = 0; d < 32; d++) acc[d] += e * vsm[s][d];
    }
    float inv = 1.0f / sum;

    float* crow = ctx + (size_t)(b * 512 + n) * 256 + h * 32;
    #pragma unroll
    for (int d = 0; d < 32; d++) crow[d] = acc[d] * inv;
}

// ---------------- final: y = h2 @ Wo2^T + bo2, broadcast over S -----------
__global__ __launch_bounds__(256) void final_kernel(
    const float* __restrict__ h2, const float* __restrict__ Wo2,
    const float* __restrict__ bo2, float* __restrict__ out)
{
    int g = blockIdx.x * 256 + threadIdx.x;   // 0..16383
    int o = g & 3;
    int row = g >> 2;        // 0..4095
    int b = row >> 9;
    int n = row & 511;

    float acc = bo2[o];
    const float* hr = h2 + (size_t)row * 128;
    const float* wr = Wo2 + (size_t)o * 128;
    #pragma unroll 8
    for (int kk = 0; kk < 128; kk++) acc += hr[kk] * wr[kk];

    float* base = out + (size_t)b * (96 * 512 * 4) + (size_t)n * 4 + o;
    #pragma unroll 4
    for (int s = 0; s < 96; s++) base[(size_t)s * 2048] = acc;
}

// ---------------- launch ----------------
extern "C" void kernel_launch(void* const* d_in, const int* in_sizes, int n_in,
                              void* d_out, int out_size)
{
    const float* spatial  = (const float*)d_in[0];   // [8,512,256]
    const float* temporal = (const float*)d_in[1];   // [8,96,256]
    const float* Ws_  = (const float*)d_in[2];       // [256,256]
    const float* bs_  = (const float*)d_in[3];
    const float* Wt_  = (const float*)d_in[4];
    const float* bt_  = (const float*)d_in[5];
    const float* Win  = (const float*)d_in[6];       // [768,256]
    const float* bin_ = (const float*)d_in[7];       // [768]
    const float* Wao  = (const float*)d_in[8];       // [256,256]
    const float* bao  = (const float*)d_in[9];
    const float* W1   = (const float*)d_in[10];      // [256,256]
    const float* b1   = (const float*)d_in[11];
    const float* Wo1  = (const float*)d_in[12];      // [128,256]
    const float* bo1  = (const float*)d_in[13];
    const float* Wo2  = (const float*)d_in[14];      // [4,128]
    const float* bo2  = (const float*)d_in[15];
    float* out = (float*)d_out;

    float *pWf, *pbf, *pq, *pk, *pv, *pctx, *patt, *pfused, *ph2;
    cudaGetSymbolAddress((void**)&pWf,    g_Wf);
    cudaGetSymbolAddress((void**)&pbf,    g_bf);
    cudaGetSymbolAddress((void**)&pq,     g_q);
    cudaGetSymbolAddress((void**)&pk,     g_k);
    cudaGetSymbolAddress((void**)&pv,     g_v);
    cudaGetSymbolAddress((void**)&pctx,   g_ctx);
    cudaGetSymbolAddress((void**)&patt,   g_att);
    cudaGetSymbolAddress((void**)&pfused, g_fused);
    cudaGetSymbolAddress((void**)&ph2,    g_h2);

    const dim3 blk(256);

    // 1) folded biases (independent of weight fold)
    fold_bias_kernel<<<96, blk>>>(Win, bin_, bs_, bt_, pbf);
    // 2) folded QKV weights, single launch (48 blocks)
    fold_gemm_kernel<<<dim3(4, 12), blk>>>(Win, Ws_, Wt_, pWf);
    // 3) q,k,v in one launch (352 blocks)
    qkv_kernel<<<352, blk>>>(spatial, temporal, pWf, pbf, pq, pk, pv);
    // 4) attention -> ctx [4096,256]
    attn_kernel<<<dim3(2, 8, 8), blk>>>(pq, pk, pv, pctx);
    // 5) attended = ctx @ Wao^T + bao
    gemm_wt_kernel<<<dim3(4, 64), blk>>>(pctx,   Wao, bao, patt,   256, 256, 0);
    // 6) fused = relu(attended @ W1^T + b1)
    gemm_wt_kernel<<<dim3(4, 64), blk>>>(patt,   W1,  b1,  pfused, 256, 256, 1);
    // 7) h2 = relu(fused @ Wo1^T + bo1)   [4096,128]
    gemm_wt_kernel<<<dim3(2, 64), blk>>>(pfused, Wo1, bo1, ph2,    128, 256, 1);
    // 8) y = h2 @ Wo2^T + bo2, broadcast to [8,96,512,4]
    final_kernel<<<64, blk>>>(ph2, Wo2, bo2, out);
}

// round 10
// speedup vs baseline: 2.1828x; 1.3252x over previous
#include <cuda_runtime.h>
#include <cstddef>

// ---------------- scratch (no allocations allowed) ----------------
__device__ float g_Wf[3 * 256 * 256];   // folded QKV weights (scale folded into Wq')
__device__ float g_Wc[256 * 256];       // folded W1@Wao
__device__ float g_bf[768];             // folded QKV biases
__device__ float g_bc[256];             // folded W1@bao + b1
__device__ float g_q[4096 * 256];
__device__ float g_k[768 * 256];
__device__ float g_v[768 * 256];
__device__ float g_ctx[4096 * 256];
__device__ float g_fused[4096 * 256];
__device__ float g_h2[4096 * 128];

#define ATTN_SCALE 0.17677669529663687f   // 1/sqrt(32)

// ---------------- fast exp: magic-number round + 2^f poly (FMA pipe) ------
__device__ __forceinline__ float fast_exp(float x) {
    float t = x * 1.4426950408889634f;           // log2(e)
    t = fminf(fmaxf(t, -120.0f), 120.0f);
    float z = t + 12582912.0f;                   // round-to-nearest int
    int   n = __float_as_int(z) - 0x4B400000;
    float f = t - (z - 12582912.0f);             // f in [-0.5, 0.5]
    float p = 1.3333558146e-3f;
    p = fmaf(p, f, 9.6181291076e-3f);
    p = fmaf(p, f, 5.5504108664e-2f);
    p = fmaf(p, f, 2.4022650695e-1f);
    p = fmaf(p, f, 6.9314718056e-1f);
    p = fmaf(p, f, 1.0f);
    return __int_as_float((n + 127) << 23) * p;  // 2^n * 2^f
}

// ---------------- double-buffered 64x64x16 GEMM tile ----------------------
// C[bm:+64, bn:+64] = A[bm:, :K] @ op(W) * oscale (+bias)(+relu)
// WT=true: W is [N,K] (uses W^T). WT=false: W is [K,N].
template <bool WT>
__device__ __forceinline__ void gemm_tile(
    const float* __restrict__ A, const float* __restrict__ W,
    const float* __restrict__ bias, float* __restrict__ C,
    int K, int N, int bm, int bn, bool relu, float oscale)
{
    __shared__ float As[2][16][64];  // As[buf][k][m]
    __shared__ float Bs[2][16][64];  // Bs[buf][k][n]
    const int tid = threadIdx.x;
    const int tm = (tid >> 4) << 2;
    const int tn = (tid & 15) << 2;
    const int am = tid >> 2, ak = (tid & 3) << 2;      // A loader
    const int wn = tid >> 2, wk = (tid & 3) << 2;      // WT loader
    const int wkk = tid >> 4, wn4 = (tid & 15) << 2;   // !WT loader

    const float* Arow = A + (size_t)(bm + am) * K + ak;
    float4 ap = *(const float4*)Arow;
    float4 wp;
    if (WT) wp = *(const float4*)(W + (size_t)(bn + wn) * K + wk);
    else    wp = *(const float4*)(W + (size_t)wkk * N + bn + wn4);

    As[0][ak + 0][am] = ap.x; As[0][ak + 1][am] = ap.y;
    As[0][ak + 2][am] = ap.z; As[0][ak + 3][am] = ap.w;
    if (WT) {
        Bs[0][wk + 0][wn] = wp.x; Bs[0][wk + 1][wn] = wp.y;
        Bs[0][wk + 2][wn] = wp.z; Bs[0][wk + 3][wn] = wp.w;
    } else {
        *(float4*)&Bs[0][wkk][wn4] = wp;
    }
    __syncthreads();

    float acc[4][4] = {};
    const int nk = K >> 4;
    int buf = 0;
    for (int s = 0; s < nk; s++) {
        if (s + 1 < nk) {   // prefetch next stage into regs
            ap = *(const float4*)(Arow + (s + 1) * 16);
            if (WT) wp = *(const float4*)(W + (size_t)(bn + wn) * K + (s + 1) * 16 + wk);
            else    wp = *(const float4*)(W + (size_t)((s + 1) * 16 + wkk) * N + bn + wn4);
        }
        #pragma unroll
        for (int kk = 0; kk < 16; kk++) {
            float4 a4 = *(const float4*)(&As[buf][kk][tm]);
            float4 w4 = *(const float4*)(&Bs[buf][kk][tn]);
            float a[4] = {a4.x, a4.y, a4.z, a4.w};
            float w[4] = {w4.x, w4.y, w4.z, w4.w};
            #pragma unroll
            for (int i = 0; i < 4; i++)
                #pragma unroll
                for (int j = 0; j < 4; j++)
                    acc[i][j] = fmaf(a[i], w[j], acc[i][j]);
        }
        if (s + 1 < nk) {   // write next stage to other buffer
            int nb = buf ^ 1;
            As[nb][ak + 0][am] = ap.x; As[nb][ak + 1][am] = ap.y;
            As[nb][ak + 2][am] = ap.z; As[nb][ak + 3][am] = ap.w;
            if (WT) {
                Bs[nb][wk + 0][wn] = wp.x; Bs[nb][wk + 1][wn] = wp.y;
                Bs[nb][wk + 2][wn] = wp.z; Bs[nb][wk + 3][wn] = wp.w;
            } else {
                *(float4*)&Bs[nb][wkk][wn4] = wp;
            }
            buf = nb;
        }
        __syncthreads();
    }

    #pragma unroll
    for (int i = 0; i < 4; i++) {
        float4 r;
        float* pr = &r.x;
        #pragma unroll
        for (int j = 0; j < 4; j++) {
            float bv = bias ? bias[bn + tn + j] : 0.0f;
            float val = fmaf(acc[i][j], 1.0f, bv) * oscale;
            // note: oscale applied to (acc+bias); for biased paths oscale==1
            if (relu) val = fmaxf(val, 0.0f);
            pr[j] = val;
        }
        *(float4*)(C + (size_t)(bm + tm + i) * N + bn + tn) = r;
    }
}

// ---------------- generic GEMM (WT path) ----------------------------------
__global__ __launch_bounds__(256) void gemm_wt_kernel(
    const float* __restrict__ A, const float* __restrict__ W,
    const float* __restrict__ bias, float* __restrict__ C,
    int N, int K, int relu)
{
    gemm_tile<true>(A, W, bias, C, K, N, blockIdx.y * 64, blockIdx.x * 64,
                    relu != 0, 1.0f);
}

// ---------------- fold kernel: all weight/bias folds in ONE launch --------
// blocks [0,48):  Wf = Win @ (Ws | Wt), q-rows (<256) scaled by ATTN_SCALE
// blocks [48,64): Wc = W1 @ Wao
// blocks [64,72): biases: bf[768] (q part scaled), bc[256]
__global__ __launch_bounds__(256) void fold_kernel(
    const float* __restrict__ Win, const float* __restrict__ Ws,
    const float* __restrict__ Wt,  const float* __restrict__ W1,
    const float* __restrict__ Wao,
    const float* __restrict__ bin, const float* __restrict__ bs,
    const float* __restrict__ bt,  const float* __restrict__ bao,
    const float* __restrict__ b1,
    float* __restrict__ Wf, float* __restrict__ Wc,
    float* __restrict__ bf, float* __restrict__ bc)
{
    int bid = blockIdx.x;
    if (bid < 48) {
        int mt = bid >> 2, nt = bid & 3;
        const float* W = (mt < 4) ? Ws : Wt;
        float osc = (mt < 4) ? ATTN_SCALE : 1.0f;
        gemm_tile<false>(Win, W, nullptr, Wf, 256, 256, mt * 64, nt * 64, false, osc);
    } else if (bid < 64) {
        int t = bid - 48, mt = t >> 2, nt = t & 3;
        gemm_tile<false>(W1, Wao, nullptr, Wc, 256, 256, mt * 64, nt * 64, false, 1.0f);
    } else {
        // bias folds: 8 blocks x 8 warps = 64 warps; 1024 outputs, 16 each
        int w = (bid - 64) * 8 + (threadIdx.x >> 5);
        int lane = threadIdx.x & 31;
        for (int rep = 0; rep < 16; rep++) {
            int o = w * 16 + rep;
            const float* row; const float* src; float add, scl; float* dst; int oi;
            if (o < 768) {
                row = Win + (size_t)o * 256;
                src = (o < 256) ? bs : bt;
                add = bin[o]; dst = bf; oi = o;
                scl = (o < 256) ? ATTN_SCALE : 1.0f;
            } else {
                int o2 = o - 768;
                row = W1 + (size_t)o2 * 256;
                src = bao; add = b1[o2]; dst = bc; oi = o2; scl = 1.0f;
            }
            float p = 0.0f;
            #pragma unroll
            for (int kk = 0; kk < 256; kk += 32)
                p = fmaf(row[kk + lane], src[kk + lane], p);
            #pragma unroll
            for (int off = 16; off; off >>= 1)
                p += __shfl_xor_sync(0xffffffffu, p, off);
            if (lane == 0) dst[oi] = (add + p) * scl;
        }
    }
}

// ---------------- merged QKV projection (one launch, 352 blocks) ----------
__global__ __launch_bounds__(256) void qkv_kernel(
    const float* __restrict__ spatial, const float* __restrict__ temporal,
    const float* __restrict__ Wf, const float* __restrict__ bf,
    float* __restrict__ q, float* __restrict__ k, float* __restrict__ v)
{
    int bid = blockIdx.x;
    const float* A; const float* W; const float* bias; float* C;
    int bx, by;
    if (bid < 256) {
        A = spatial;  W = Wf;           bias = bf;       C = q;
        bx = bid & 3; by = bid >> 2;
    } else if (bid < 304) {
        int t = bid - 256;
        A = temporal; W = Wf + 65536;   bias = bf + 256; C = k;
        bx = t & 3;   by = t >> 2;
    } else {
        int t = bid - 304;
        A = temporal; W = Wf + 131072;  bias = bf + 512; C = v;
        bx = t & 3;   by = t >> 2;
    }
    gemm_tile<true>(A, W, bias, C, 256, 256, by * 64, bx * 64, false, 1.0f);
}

// ---------------- attention: streaming softmax, no spills, no MUFU --------
// q already scaled. One thread per q-row; grid (4, NH, B), 128 thr.
__global__ __launch_bounds__(128) void attn_kernel(
    const float* __restrict__ q, const float* __restrict__ k,
    const float* __restrict__ v, float* __restrict__ ctx)
{
    __shared__ float ks[96][32];
    __shared__ float vs[96][32];
    const int b = blockIdx.z, h = blockIdx.y;
    const size_t kvbase = (size_t)b * 96 * 256 + h * 32;
    for (int i = threadIdx.x; i < 96 * 8; i += 128) {
        int s = i >> 3, d4 = (i & 7) << 2;
        *(float4*)&ks[s][d4] = *(const float4*)(k + kvbase + (size_t)s * 256 + d4);
        *(float4*)&vs[s][d4] = *(const float4*)(v + kvbase + (size_t)s * 256 + d4);
    }
    __syncthreads();

    const int n = blockIdx.x * 128 + threadIdx.x;
    const float* qrow = q + (size_t)(b * 512 + n) * 256 + h * 32;
    float qv[32];
    #pragma unroll
    for (int d4 = 0; d4 < 8; d4++) {
        float4 t = *(const float4*)(qrow + d4 * 4);
        qv[d4 * 4 + 0] = t.x; qv[d4 * 4 + 1] = t.y;
        qv[d4 * 4 + 2] = t.z; qv[d4 * 4 + 3] = t.w;
    }

    float acc[32];
    #pragma unroll
    for (int d = 0; d < 32; d++) acc[d] = 0.0f;
    float sum = 0.0f;

    #pragma unroll 2
    for (int s = 0; s < 96; s++) {
        float a0 = 0.f, a1 = 0.f, a2 = 0.f, a3 = 0.f;
        #pragma unroll
        for (int d4 = 0; d4 < 8; d4++) {
            float4 k4 = *(const float4*)(&ks[s][d4 * 4]);
            a0 = fmaf(qv[d4 * 4 + 0], k4.x, a0);
            a1 = fmaf(qv[d4 * 4 + 1], k4.y, a1);
            a2 = fmaf(qv[d4 * 4 + 2], k4.z, a2);
            a3 = fmaf(qv[d4 * 4 + 3], k4.w, a3);
        }
        float e = fast_exp((a0 + a1) + (a2 + a3));   // logits bounded; clamp inside
        sum += e;
        #pragma unroll
        for (int d4 = 0; d4 < 8; d4++) {
            float4 v4 = *(const float4*)(&vs[s][d4 * 4]);
            acc[d4 * 4 + 0] = fmaf(e, v4.x, acc[d4 * 4 + 0]);
            acc[d4 * 4 + 1] = fmaf(e, v4.y, acc[d4 * 4 + 1]);
            acc[d4 * 4 + 2] = fmaf(e, v4.z, acc[d4 * 4 + 2]);
            acc[d4 * 4 + 3] = fmaf(e, v4.w, acc[d4 * 4 + 3]);
        }
    }
    float inv = 1.0f / sum;

    float* crow = ctx + (size_t)(b * 512 + n) * 256 + h * 32;
    #pragma unroll
    for (int d4 = 0; d4 < 8; d4++) {
        float4 r;
        r.x = acc[d4 * 4 + 0] * inv; r.y = acc[d4 * 4 + 1] * inv;
        r.z = acc[d4 * 4 + 2] * inv; r.w = acc[d4 * 4 + 3] * inv;
        *(float4*)(crow + d4 * 4) = r;
    }
}

// ---------------- final: y = h2 @ Wo2^T + bo2, broadcast over S -----------
__global__ __launch_bounds__(256) void final_kernel(
    const float* __restrict__ h2, const float* __restrict__ Wo2,
    const float* __restrict__ bo2, float* __restrict__ out)
{
    int g = blockIdx.x * 256 + threadIdx.x;   // 0..16383
    int o = g & 3;
    int row = g >> 2;        // 0..4095
    int b = row >> 9;
    int n = row & 511;

    float acc = bo2[o];
    const float* hr = h2 + (size_t)row * 128;
    const float* wr = Wo2 + (size_t)o * 128;
    #pragma unroll 8
    for (int kk = 0; kk < 128; kk++) acc = fmaf(hr[kk], wr[kk], acc);

    float* base = out + (size_t)b * (96 * 512 * 4) + (size_t)n * 4 + o;
    #pragma unroll 4
    for (int s = 0; s < 96; s++) base[(size_t)s * 2048] = acc;
}

// ---------------- launch ----------------
extern "C" void kernel_launch(void* const* d_in, const int* in_sizes, int n_in,
                              void* d_out, int out_size)
{
    const float* spatial  = (const float*)d_in[0];   // [8,512,256]
    const float* temporal = (const float*)d_in[1];   // [8,96,256]
    const float* Ws_  = (const float*)d_in[2];       // [256,256]
    const float* bs_  = (const float*)d_in[3];
    const float* Wt_  = (const float*)d_in[4];
    const float* bt_  = (const float*)d_in[5];
    const float* Win  = (const float*)d_in[6];       // [768,256]
    const float* bin_ = (const float*)d_in[7];       // [768]
    const float* Wao  = (const float*)d_in[8];       // [256,256]
    const float* bao  = (const float*)d_in[9];
    const float* W1   = (const float*)d_in[10];      // [256,256]
    const float* b1   = (const float*)d_in[11];
    const float* Wo1  = (const float*)d_in[12];      // [128,256]
    const float* bo1  = (const float*)d_in[13];
    const float* Wo2  = (const float*)d_in[14];      // [4,128]
    const float* bo2  = (const float*)d_in[15];
    float* out = (float*)d_out;

    float *pWf, *pWc, *pbf, *pbc, *pq, *pk, *pv, *pctx, *pfused, *ph2;
    cudaGetSymbolAddress((void**)&pWf,    g_Wf);
    cudaGetSymbolAddress((void**)&pWc,    g_Wc);
    cudaGetSymbolAddress((void**)&pbf,    g_bf);
    cudaGetSymbolAddress((void**)&pbc,    g_bc);
    cudaGetSymbolAddress((void**)&pq,     g_q);
    cudaGetSymbolAddress((void**)&pk,     g_k);
    cudaGetSymbolAddress((void**)&pv,     g_v);
    cudaGetSymbolAddress((void**)&pctx,   g_ctx);
    cudaGetSymbolAddress((void**)&pfused, g_fused);
    cudaGetSymbolAddress((void**)&ph2,    g_h2);

    const dim3 blk(256);

    // 1) all folds: Wf (Win@Ws|Wt, scale folded), Wc (W1@Wao), bf, bc
    fold_kernel<<<72, blk>>>(Win, Ws_, Wt_, W1, Wao,
                             bin_, bs_, bt_, bao, b1,
                             pWf, pWc, pbf, pbc);
    // 2) q,k,v in one launch (q pre-scaled)
    qkv_kernel<<<352, blk>>>(spatial, temporal, pWf, pbf, pq, pk, pv);
    // 3) attention -> ctx [4096,256]
    attn_kernel<<<dim3(4, 8, 8), 128>>>(pq, pk, pv, pctx);
    // 4) fused = relu(ctx @ Wc^T + bc)   (Wao+W1 folded)
    gemm_wt_kernel<<<dim3(4, 64), blk>>>(pctx,   pWc, pbc, pfused, 256, 256, 1);
    // 5) h2 = relu(fused @ Wo1^T + bo1)  [4096,128]
    gemm_wt_kernel<<<dim3(2, 64), blk>>>(pfused, Wo1, bo1, ph2,    128, 256, 1);
    // 6) y = h2 @ Wo2^T + bo2, broadcast to [8,96,512,4]
    final_kernel<<<64, blk>>>(ph2, Wo2, bo2, out);
}

// round 11
// speedup vs baseline: 2.1834x; 1.0003x over previous
#include <cuda_runtime.h>
#include <cstddef>

// ---------------- scratch (no allocations allowed) ----------------
__device__ float g_Wf[3 * 256 * 256];   // folded QKV weights (scale folded into Wq')
__device__ float g_Wc[256 * 256];       // folded W1@Wao
__device__ float g_bf[768];             // folded QKV biases
__device__ float g_bc[256];             // folded W1@bao + b1
__device__ float g_q[4096 * 256];
__device__ float g_k[768 * 256];
__device__ float g_v[768 * 256];
__device__ float g_ctx[4096 * 256];
__device__ float g_fused[4096 * 256];
__device__ float g_h2[4096 * 128];

#define ATTN_SCALE 0.17677669529663687f   // 1/sqrt(32)

// ---------------- fast exp: magic-number round + 2^f poly (FMA pipe) ------
__device__ __forceinline__ float fast_exp(float x) {
    float t = x * 1.4426950408889634f;           // log2(e)
    t = fminf(fmaxf(t, -120.0f), 120.0f);
    float z = t + 12582912.0f;                   // round-to-nearest int
    int   n = __float_as_int(z) - 0x4B400000;
    float f = t - (z - 12582912.0f);             // f in [-0.5, 0.5]
    float p = 1.3333558146e-3f;
    p = fmaf(p, f, 9.6181291076e-3f);
    p = fmaf(p, f, 5.5504108664e-2f);
    p = fmaf(p, f, 2.4022650695e-1f);
    p = fmaf(p, f, 6.9314718056e-1f);
    p = fmaf(p, f, 1.0f);
    return __int_as_float((n + 127) << 23) * p;  // 2^n * 2^f
}

// ---------------- double-buffered 64x64x16 GEMM tile ----------------------
// C[bm:+64, bn:+64] = A[bm:, :K] @ op(W) * oscale (+bias)(+relu)
// WT=true: W is [N,K] (uses W^T). WT=false: W is [K,N].
template <bool WT>
__device__ __forceinline__ void gemm_tile(
    const float* __restrict__ A, const float* __restrict__ W,
    const float* __restrict__ bias, float* __restrict__ C,
    int K, int N, int bm, int bn, bool relu, float oscale)
{
    __shared__ float As[2][16][64];  // As[buf][k][m]
    __shared__ float Bs[2][16][64];  // Bs[buf][k][n]
    const int tid = threadIdx.x;
    const int tm = (tid >> 4) << 2;
    const int tn = (tid & 15) << 2;
    const int am = tid >> 2, ak = (tid & 3) << 2;      // A loader
    const int wn = tid >> 2, wk = (tid & 3) << 2;      // WT loader
    const int wkk = tid >> 4, wn4 = (tid & 15) << 2;   // !WT loader

    const float* Arow = A + (size_t)(bm + am) * K + ak;
    float4 ap = *(const float4*)Arow;
    float4 wp;
    if (WT) wp = *(const float4*)(W + (size_t)(bn + wn) * K + wk);
    else    wp = *(const float4*)(W + (size_t)wkk * N + bn + wn4);

    As[0][ak + 0][am] = ap.x; As[0][ak + 1][am] = ap.y;
    As[0][ak + 2][am] = ap.z; As[0][ak + 3][am] = ap.w;
    if (WT) {
        Bs[0][wk + 0][wn] = wp.x; Bs[0][wk + 1][wn] = wp.y;
        Bs[0][wk + 2][wn] = wp.z; Bs[0][wk + 3][wn] = wp.w;
    } else {
        *(float4*)&Bs[0][wkk][wn4] = wp;
    }
    __syncthreads();

    float acc[4][4] = {};
    const int nk = K >> 4;
    int buf = 0;
    for (int s = 0; s < nk; s++) {
        if (s + 1 < nk) {   // prefetch next stage into regs
            ap = *(const float4*)(Arow + (s + 1) * 16);
            if (WT) wp = *(const float4*)(W + (size_t)(bn + wn) * K + (s + 1) * 16 + wk);
            else    wp = *(const float4*)(W + (size_t)((s + 1) * 16 + wkk) * N + bn + wn4);
        }
        #pragma unroll
        for (int kk = 0; kk < 16; kk++) {
            float4 a4 = *(const float4*)(&As[buf][kk][tm]);
            float4 w4 = *(const float4*)(&Bs[buf][kk][tn]);
            float a[4] = {a4.x, a4.y, a4.z, a4.w};
            float w[4] = {w4.x, w4.y, w4.z, w4.w};
            #pragma unroll
            for (int i = 0; i < 4; i++)
                #pragma unroll
                for (int j = 0; j < 4; j++)
                    acc[i][j] = fmaf(a[i], w[j], acc[i][j]);
        }
        if (s + 1 < nk) {   // write next stage to other buffer
            int nb = buf ^ 1;
            As[nb][ak + 0][am] = ap.x; As[nb][ak + 1][am] = ap.y;
            As[nb][ak + 2][am] = ap.z; As[nb][ak + 3][am] = ap.w;
            if (WT) {
                Bs[nb][wk + 0][wn] = wp.x; Bs[nb][wk + 1][wn] = wp.y;
                Bs[nb][wk + 2][wn] = wp.z; Bs[nb][wk + 3][wn] = wp.w;
            } else {
                *(float4*)&Bs[nb][wkk][wn4] = wp;
            }
            buf = nb;
        }
        __syncthreads();
    }

    #pragma unroll
    for (int i = 0; i < 4; i++) {
        float4 r;
        float* pr = &r.x;
        #pragma unroll
        for (int j = 0; j < 4; j++) {
            float bv = bias ? bias[bn + tn + j] : 0.0f;
            float val = fmaf(acc[i][j], 1.0f, bv) * oscale;
            // note: oscale applied to (acc+bias); for biased paths oscale==1
            if (relu) val = fmaxf(val, 0.0f);
            pr[j] = val;
        }
        *(float4*)(C + (size_t)(bm + tm + i) * N + bn + tn) = r;
    }
}

// ---------------- generic GEMM (WT path) ----------------------------------
__global__ __launch_bounds__(256) void gemm_wt_kernel(
    const float* __restrict__ A, const float* __restrict__ W,
    const float* __restrict__ bias, float* __restrict__ C,
    int N, int K, int relu)
{
    gemm_tile<true>(A, W, bias, C, K, N, blockIdx.y * 64, blockIdx.x * 64,
                    relu != 0, 1.0f);
}

// ---------------- fold kernel: all weight/bias folds in ONE launch --------
// blocks [0,48):  Wf = Win @ (Ws | Wt), q-rows (<256) scaled by ATTN_SCALE
// blocks [48,64): Wc = W1 @ Wao
// blocks [64,72): biases: bf[768] (q part scaled), bc[256]
__global__ __launch_bounds__(256) void fold_kernel(
    const float* __restrict__ Win, const float* __restrict__ Ws,
    const float* __restrict__ Wt,  const float* __restrict__ W1,
    const float* __restrict__ Wao,
    const float* __restrict__ bin, const float* __restrict__ bs,
    const float* __restrict__ bt,  const float* __restrict__ bao,
    const float* __restrict__ b1,
    float* __restrict__ Wf, float* __restrict__ Wc,
    float* __restrict__ bf, float* __restrict__ bc)
{
    int bid = blockIdx.x;
    if (bid < 48) {
        int mt = bid >> 2, nt = bid & 3;
        const float* W = (mt < 4) ? Ws : Wt;
        float osc = (mt < 4) ? ATTN_SCALE : 1.0f;
        gemm_tile<false>(Win, W, nullptr, Wf, 256, 256, mt * 64, nt * 64, false, osc);
    } else if (bid < 64) {
        int t = bid - 48, mt = t >> 2, nt = t & 3;
        gemm_tile<false>(W1, Wao, nullptr, Wc, 256, 256, mt * 64, nt * 64, false, 1.0f);
    } else {
        // bias folds: 8 blocks x 8 warps = 64 warps; 1024 outputs, 16 each
        int w = (bid - 64) * 8 + (threadIdx.x >> 5);
        int lane = threadIdx.x & 31;
        for (int rep = 0; rep < 16; rep++) {
            int o = w * 16 + rep;
            const float* row; const float* src; float add, scl; float* dst; int oi;
            if (o < 768) {
                row = Win + (size_t)o * 256;
                src = (o < 256) ? bs : bt;
                add = bin[o]; dst = bf; oi = o;
                scl = (o < 256) ? ATTN_SCALE : 1.0f;
            } else {
                int o2 = o - 768;
                row = W1 + (size_t)o2 * 256;
                src = bao; add = b1[o2]; dst = bc; oi = o2; scl = 1.0f;
            }
            float p = 0.0f;
            #pragma unroll
            for (int kk = 0; kk < 256; kk += 32)
                p = fmaf(row[kk + lane], src[kk + lane], p);
            #pragma unroll
            for (int off = 16; off; off >>= 1)
                p += __shfl_xor_sync(0xffffffffu, p, off);
            if (lane == 0) dst[oi] = (add + p) * scl;
        }
    }
}

// ---------------- merged QKV projection (one launch, 352 blocks) ----------
__global__ __launch_bounds__(256) void qkv_kernel(
    const float* __restrict__ spatial, const float* __restrict__ temporal,
    const float* __restrict__ Wf, const float* __restrict__ bf,
    float* __restrict__ q, float* __restrict__ k, float* __restrict__ v)
{
    int bid = blockIdx.x;
    const float* A; const float* W; const float* bias; float* C;
    int bx, by;
    if (bid < 256) {
        A = spatial;  W = Wf;           bias = bf;       C = q;
        bx = bid & 3; by = bid >> 2;
    } else if (bid < 304) {
        int t = bid - 256;
        A = temporal; W = Wf + 65536;   bias = bf + 256; C = k;
        bx = t & 3;   by = t >> 2;
    } else {
        int t = bid - 304;
        A = temporal; W = Wf + 131072;  bias = bf + 512; C = v;
        bx = t & 3;   by = t >> 2;
    }
    gemm_tile<true>(A, W, bias, C, 256, 256, by * 64, bx * 64, false, 1.0f);
}

// ---------------- attention: streaming softmax, no spills, no MUFU --------
// q already scaled. One thread per q-row; grid (4, NH, B), 128 thr.
__global__ __launch_bounds__(128) void attn_kernel(
    const float* __restrict__ q, const float* __restrict__ k,
    const float* __restrict__ v, float* __restrict__ ctx)
{
    __shared__ float ks[96][32];
    __shared__ float vs[96][32];
    const int b = blockIdx.z, h = blockIdx.y;
    const size_t kvbase = (size_t)b * 96 * 256 + h * 32;
    for (int i = threadIdx.x; i < 96 * 8; i += 128) {
        int s = i >> 3, d4 = (i & 7) << 2;
        *(float4*)&ks[s][d4] = *(const float4*)(k + kvbase + (size_t)s * 256 + d4);
        *(float4*)&vs[s][d4] = *(const float4*)(v + kvbase + (size_t)s * 256 + d4);
    }
    __syncthreads();

    const int n = blockIdx.x * 128 + threadIdx.x;
    const float* qrow = q + (size_t)(b * 512 + n) * 256 + h * 32;
    float qv[32];
    #pragma unroll
    for (int d4 = 0; d4 < 8; d4++) {
        float4 t = *(const float4*)(qrow + d4 * 4);
        qv[d4 * 4 + 0] = t.x; qv[d4 * 4 + 1] = t.y;
        qv[d4 * 4 + 2] = t.z; qv[d4 * 4 + 3] = t.w;
    }

    float acc[32];
    #pragma unroll
    for (int d = 0; d < 32; d++) acc[d] = 0.0f;
    float sum = 0.0f;

    #pragma unroll 2
    for (int s = 0; s < 96; s++) {
        float a0 = 0.f, a1 = 0.f, a2 = 0.f, a3 = 0.f;
        #pragma unroll
        for (int d4 = 0; d4 < 8; d4++) {
            float4 k4 = *(const float4*)(&ks[s][d4 * 4]);
            a0 = fmaf(qv[d4 * 4 + 0], k4.x, a0);
            a1 = fmaf(qv[d4 * 4 + 1], k4.y, a1);
            a2 = fmaf(qv[d4 * 4 + 2], k4.z, a2);
            a3 = fmaf(qv[d4 * 4 + 3], k4.w, a3);
        }
        float e = fast_exp((a0 + a1) + (a2 + a3));   // logits bounded; clamp inside
        sum += e;
        #pragma unroll
        for (int d4 = 0; d4 < 8; d4++) {
            float4 v4 = *(const float4*)(&vs[s][d4 * 4]);
            acc[d4 * 4 + 0] = fmaf(e, v4.x, acc[d4 * 4 + 0]);
            acc[d4 * 4 + 1] = fmaf(e, v4.y, acc[d4 * 4 + 1]);
            acc[d4 * 4 + 2] = fmaf(e, v4.z, acc[d4 * 4 + 2]);
            acc[d4 * 4 + 3] = fmaf(e, v4.w, acc[d4 * 4 + 3]);
        }
    }
    float inv = 1.0f / sum;

    float* crow = ctx + (size_t)(b * 512 + n) * 256 + h * 32;
    #pragma unroll
    for (int d4 = 0; d4 < 8; d4++) {
        float4 r;
        r.x = acc[d4 * 4 + 0] * inv; r.y = acc[d4 * 4 + 1] * inv;
        r.z = acc[d4 * 4 + 2] * inv; r.w = acc[d4 * 4 + 3] * inv;
        *(float4*)(crow + d4 * 4) = r;
    }
}

// ---------------- final: y = h2 @ Wo2^T + bo2, broadcast over S -----------
__global__ __launch_bounds__(256) void final_kernel(
    const float* __restrict__ h2, const float* __restrict__ Wo2,
    const float* __restrict__ bo2, float* __restrict__ out)
{
    int g = blockIdx.x * 256 + threadIdx.x;   // 0..16383
    int o = g & 3;
    int row = g >> 2;        // 0..4095
    int b = row >> 9;
    int n = row & 511;

    float acc = bo2[o];
    const float* hr = h2 + (size_t)row * 128;
    const float* wr = Wo2 + (size_t)o * 128;
    #pragma unroll 8
    for (int kk = 0; kk < 128; kk++) acc = fmaf(hr[kk], wr[kk], acc);

    float* base = out + (size_t)b * (96 * 512 * 4) + (size_t)n * 4 + o;
    #pragma unroll 4
    for (int s = 0; s < 96; s++) base[(size_t)s * 2048] = acc;
}

// ---------------- launch ----------------
extern "C" void kernel_launch(void* const* d_in, const int* in_sizes, int n_in,
                              void* d_out, int out_size)
{
    const float* spatial  = (const float*)d_in[0];   // [8,512,256]
    const float* temporal = (const float*)d_in[1];   // [8,96,256]
    const float* Ws_  = (const float*)d_in[2];       // [256,256]
    const float* bs_  = (const float*)d_in[3];
    const float* Wt_  = (const float*)d_in[4];
    const float* bt_  = (const float*)d_in[5];
    const float* Win  = (const float*)d_in[6];       // [768,256]
    const float* bin_ = (const float*)d_in[7];       // [768]
    const float* Wao  = (const float*)d_in[8];       // [256,256]
    const float* bao  = (const float*)d_in[9];
    const float* W1   = (const float*)d_in[10];      // [256,256]
    const float* b1   = (const float*)d_in[11];
    const float* Wo1  = (const float*)d_in[12];      // [128,256]
    const float* bo1  = (const float*)d_in[13];
    const float* Wo2  = (const float*)d_in[14];      // [4,128]
    const float* bo2  = (const float*)d_in[15];
    float* out = (float*)d_out;

    float *pWf, *pWc, *pbf, *pbc, *pq, *pk, *pv, *pctx, *pfused, *ph2;
    cudaGetSymbolAddress((void**)&pWf,    g_Wf);
    cudaGetSymbolAddress((void**)&pWc,    g_Wc);
    cudaGetSymbolAddress((void**)&pbf,    g_bf);
    cudaGetSymbolAddress((void**)&pbc,    g_bc);
    cudaGetSymbolAddress((void**)&pq,     g_q);
    cudaGetSymbolAddress((void**)&pk,     g_k);
    cudaGetSymbolAddress((void**)&pv,     g_v);
    cudaGetSymbolAddress((void**)&pctx,   g_ctx);
    cudaGetSymbolAddress((void**)&pfused, g_fused);
    cudaGetSymbolAddress((void**)&ph2,    g_h2);

    const dim3 blk(256);

    // 1) all folds: Wf (Win@Ws|Wt, scale folded), Wc (W1@Wao), bf, bc
    fold_kernel<<<72, blk>>>(Win, Ws_, Wt_, W1, Wao,
                             bin_, bs_, bt_, bao, b1,
                             pWf, pWc, pbf, pbc);
    // 2) q,k,v in one launch (q pre-scaled)
    qkv_kernel<<<352, blk>>>(spatial, temporal, pWf, pbf, pq, pk, pv);
    // 3) attention -> ctx [4096,256]
    attn_kernel<<<dim3(4, 8, 8), 128>>>(pq, pk, pv, pctx);
    // 4) fused = relu(ctx @ Wc^T + bc)   (Wao+W1 folded)
    gemm_wt_kernel<<<dim3(4, 64), blk>>>(pctx,   pWc, pbc, pfused, 256, 256, 1);
    // 5) h2 = relu(fused @ Wo1^T + bo1)  [4096,128]
    gemm_wt_kernel<<<dim3(2, 64), blk>>>(pfused, Wo1, bo1, ph2,    128, 256, 1);
    // 6) y = h2 @ Wo2^T + bo2, broadcast to [8,96,512,4]
    final_kernel<<<64, blk>>>(ph2, Wo2, bo2, out);
}